// round 14
// baseline (speedup 1.0000x reference)
#include <cuda_runtime.h>

// Fused cosine-score attention, single query. Two kernels.
//
// stage1: persistent blocks + atomic WORK-STEALING. Five pipeline variants
//   all converged at 5.2 TB/s => bandwidth is at its ceiling; the remaining
//   loss is the tail (static 2048-chunk/148-block assignment has 7% built-in
//   imbalance x ~1.1 per-SM spread). Blocks grab 16-row chunks from a global
//   ticket (double-buffered grab hides the 318cyc atomic latency); warps use
//   the proven register-LDG row body. Block tree-reduce -> 148 partials.
// stage2: 16x512 deterministic reduction (best measured, 4.16us) + resets
//   the ticket for the next graph replay (runs after stage1 in stream order).

#define NBLK 148
#define NTHR 512
#define WPB  (NTHR / 32)           // 16 warps per block
#define H 1024
#define HV4 (H / 4)                // 256 float4 per row
#define CROWS 16                   // rows per stolen chunk (one per warp)

__device__ float4   g_partial[NBLK][HV4];   // 606 KB scratch
__device__ unsigned g_ticket;                // zero-init; stage2 resets it

__global__ __launch_bounds__(NTHR, 1)
void bahdanau_stage1(const float* __restrict__ q,
                     const float* __restrict__ keys, int S) {
    const int wib  = threadIdx.x >> 5;
    const int lane = threadIdx.x & 31;

    __shared__ float4   red[8][HV4];   // 32 KB, reused across reduction
    __shared__ unsigned s_chunk[2];    // double-buffered stolen tickets

    const int nchunk = S / CROWS;      // 32768/16 = 2048

    // q slice for this lane + |q|
    const float4* q4 = (const float4*)q;
    float4 qv[8];
    float qss = 0.f;
#pragma unroll
    for (int i = 0; i < 8; i++) {
        qv[i] = q4[i * 32 + lane];
        qss += qv[i].x * qv[i].x + qv[i].y * qv[i].y +
               qv[i].z * qv[i].z + qv[i].w * qv[i].w;
    }
#pragma unroll
    for (int o = 16; o; o >>= 1) qss += __shfl_xor_sync(0xffffffffu, qss, o);
    const float inv_qn = rsqrtf(qss);

    float4 acc[8];
#pragma unroll
    for (int i = 0; i < 8; i++) acc[i] = make_float4(0.f, 0.f, 0.f, 0.f);

    // Prologue: grab the first chunk.
    if (threadIdx.x == 0) s_chunk[0] = atomicAdd(&g_ticket, 1u);
    __syncthreads();

    int buf = 0;
    for (;;) {
        const int c = (int)s_chunk[buf];
        if (c >= nchunk) break;

        // Steal the next chunk while this one streams (latency hidden).
        if (threadIdx.x == 0) s_chunk[buf ^ 1] = atomicAdd(&g_ticket, 1u);

        const int s = c * CROWS + wib;           // this warp's row
        const float4* row = (const float4*)(keys + (size_t)s * H);
        float4 kv[8];
        float dot = 0.f, kss = 0.f;
#pragma unroll
        for (int i = 0; i < 8; i++) {
            kv[i] = row[i * 32 + lane];
            dot += kv[i].x * qv[i].x + kv[i].y * qv[i].y +
                   kv[i].z * qv[i].z + kv[i].w * qv[i].w;
            kss += kv[i].x * kv[i].x + kv[i].y * kv[i].y +
                   kv[i].z * kv[i].z + kv[i].w * kv[i].w;
        }
#pragma unroll
        for (int o = 16; o; o >>= 1) {
            dot += __shfl_xor_sync(0xffffffffu, dot, o);
            kss += __shfl_xor_sync(0xffffffffu, kss, o);
        }
        const float score = dot * inv_qn * rsqrtf(kss);
#pragma unroll
        for (int i = 0; i < 8; i++) {
            acc[i].x += score * kv[i].x;
            acc[i].y += score * kv[i].y;
            acc[i].z += score * kv[i].z;
            acc[i].w += score * kv[i].w;
        }

        __syncthreads();        // next ticket visible; all done with s_chunk[buf]
        buf ^= 1;
    }

    // Block tree reduction: 16 -> 8 -> 4 -> 2 -> 1 warps.
#pragma unroll
    for (int half = 8; half >= 1; half >>= 1) {
        if (wib >= half && wib < 2 * half) {
#pragma unroll
            for (int i = 0; i < 8; i++)
                red[wib - half][i * 32 + lane] = acc[i];
        }
        __syncthreads();
        if (wib < half) {
#pragma unroll
            for (int i = 0; i < 8; i++) {
                float4 v = red[wib][i * 32 + lane];
                acc[i].x += v.x; acc[i].y += v.y;
                acc[i].z += v.z; acc[i].w += v.w;
            }
        }
        __syncthreads();
    }

    if (wib == 0) {
#pragma unroll
        for (int i = 0; i < 8; i++)
            g_partial[blockIdx.x][i * 32 + lane] = acc[i];
    }
}

// stage2: out[h] = sum_{b<148} g_partial[b][h] (coalesced: lane -> column).
// 16 blocks x 512 threads. Also resets the work-stealing ticket for the next
// graph replay (stage2 always runs after stage1 completes, stream order).
__global__ __launch_bounds__(512)
void bahdanau_stage2(float* __restrict__ out) {
    if (blockIdx.x == 0 && threadIdx.x == 0) g_ticket = 0u;

    const int col = blockIdx.x * 64 + (threadIdx.x & 63);
    const int g   = threadIdx.x >> 6;   // 0..7
    const float* part = (const float*)g_partial;

    float s = 0.f;
#pragma unroll
    for (int b = 0; b < 19; b++) {      // 19*8 = 152 >= 148
        int p = g + b * 8;
        if (p < NBLK) s += part[(size_t)p * H + col];
    }

    __shared__ float sh[512];
    sh[threadIdx.x] = s;
    __syncthreads();
#pragma unroll
    for (int stride = 256; stride >= 64; stride >>= 1) {
        if (threadIdx.x < stride) sh[threadIdx.x] += sh[threadIdx.x + stride];
        __syncthreads();
    }
    if (threadIdx.x < 64) out[blockIdx.x * 64 + threadIdx.x] = sh[threadIdx.x];
}

extern "C" void kernel_launch(void* const* d_in, const int* in_sizes, int n_in,
                              void* d_out, int out_size) {
    const float* q    = (const float*)d_in[0];   // [1, 1024]
    const float* keys = (const float*)d_in[1];   // [S, 1024]
    const int S = in_sizes[1] / H;

    bahdanau_stage1<<<NBLK, NTHR>>>(q, keys, S);
    bahdanau_stage2<<<16, 512>>>((float*)d_out);
}